// round 5
// baseline (speedup 1.0000x reference)
#include <cuda_runtime.h>
#include <cuda_bf16.h>
#include <math.h>

// ---------------------------------------------------------------------------
// Problem constants (shapes fixed by the dataset)
// ---------------------------------------------------------------------------
#define MAXN 500000
#define MAXV 50000

// Scratch (device globals: allocation-free rule)
__device__ float        g_pf2[(size_t)MAXN * 128];     // 256 MB point features stage-1
__device__ unsigned int g_voxmax[(size_t)MAXV * 128];  // segment-max #1 (bits of nonneg f32)
__device__ float        g_voxw[(size_t)MAXV * 128];    // relu(vox @ wv1 + bv1)
__device__ unsigned int g_vox2[(size_t)MAXV * 256];    // segment-max #2

// ---------------------------------------------------------------------------
// Packed f32x2 helpers (Blackwell FFMA2 — 2x fp32 FMA rate)
// ---------------------------------------------------------------------------
__device__ __forceinline__ unsigned long long pack2(float x) {
    unsigned long long r;
    asm("mov.b64 %0, {%1, %1};" : "=l"(r) : "f"(x));
    return r;
}
__device__ __forceinline__ void unpack2(unsigned long long v, float &lo, float &hi) {
    asm("mov.b64 {%0, %1}, %2;" : "=f"(lo), "=f"(hi) : "l"(v));
}
__device__ __forceinline__ unsigned long long ffma2(unsigned long long a,
                                                    unsigned long long b,
                                                    unsigned long long c) {
    unsigned long long d;
    asm("fma.rn.f32x2 %0, %1, %2, %3;" : "=l"(d) : "l"(a), "l"(b), "l"(c));
    return d;
}

__device__ __forceinline__ float sigm(float s) { return 1.0f / (1.0f + expf(-s)); }

// ---------------------------------------------------------------------------
// Kernel 0: zero the two segment-max buffers
// ---------------------------------------------------------------------------
__global__ void zero_kernel(int V) {
    int i = blockIdx.x * blockDim.x + threadIdx.x;
    int n1 = V * 32;  // voxmax in uint4 units (V*128/4)
    int n2 = V * 64;  // vox2   in uint4 units (V*256/4)
    uint4 z = {0u, 0u, 0u, 0u};
    if (i < n1)            ((uint4 *)g_voxmax)[i]      = z;
    else if (i < n1 + n2)  ((uint4 *)g_vox2)[i - n1]   = z;
}

// ---------------------------------------------------------------------------
// Kernel 1: per-point stage-1 MLPs + gates -> pf2 (N,128) + atomic seg-max #1
// ---------------------------------------------------------------------------
__global__ __launch_bounds__(128, 1) void stage1_kernel(
    const float *__restrict__ inp, const int *__restrict__ v2p,
    const float *__restrict__ w1x, const float *__restrict__ b1x,
    const float *__restrict__ w2x, const float *__restrict__ b2x,
    const float *__restrict__ w1r, const float *__restrict__ b1r,
    const float *__restrict__ w2r, const float *__restrict__ b2r,
    const float *__restrict__ wax, const float *__restrict__ bax,
    const float *__restrict__ war, const float *__restrict__ bar,
    int N)
{
    __shared__ float sW[8832];
    const int t = threadIdx.x;
    {
        const float *srcs[12] = {w1x, b1x, w2x, b2x, w1r, b1r, w2r, b2r, wax, bax, war, bar};
        const int offs[13] = {0, 192, 256, 2304, 2336, 2528, 2592, 4640, 4672, 6720, 6752, 8800, 8832};
        for (int a = 0; a < 12; a++) {
            int n = offs[a + 1] - offs[a];
            for (int s = t; s < n; s += 128) sW[offs[a] + s] = srcs[a][s];
        }
    }
    __syncthreads();

    int i = blockIdx.x * 128 + t;
    if (i >= N) return;

    const float *cw1x = sW;        const float *cb1x = sW + 192;
    const float *cw2x = sW + 256;  const float *cb2x = sW + 2304;
    const float *cw1r = sW + 2336; const float *cb1r = sW + 2528;
    const float *cw2r = sW + 2592; const float *cb2r = sW + 4640;
    const float *cwax = sW + 4672; const float *cbax = sW + 6720;
    const float *cwar = sW + 6752; const float *cbar = sW + 8800;

    const float *pi = inp + (size_t)i * 6;
    float p0 = pi[0], p1 = pi[1], p2 = pi[2], p3 = pi[3], p4 = pi[4], p5 = pi[5];

    float fx[32], fr[32];
    {
        float h[64];
#pragma unroll
        for (int j = 0; j < 64; j++)
            h[j] = fmaxf(cb1x[j] + p0 * cw1x[j] + p1 * cw1x[64 + j] + p2 * cw1x[128 + j], 0.0f);
#pragma unroll
        for (int j = 0; j < 32; j++) fx[j] = cb2x[j];
#pragma unroll
        for (int k = 0; k < 64; k++) {
            float hk = h[k];
#pragma unroll
            for (int j = 0; j < 32; j++) fx[j] = fmaf(hk, cw2x[k * 32 + j], fx[j]);
        }
#pragma unroll
        for (int j = 0; j < 32; j++) fx[j] = fmaxf(fx[j], 0.0f);
    }
    {
        float h[64];
#pragma unroll
        for (int j = 0; j < 64; j++)
            h[j] = fmaxf(cb1r[j] + p3 * cw1r[j] + p4 * cw1r[64 + j] + p5 * cw1r[128 + j], 0.0f);
#pragma unroll
        for (int j = 0; j < 32; j++) fr[j] = cb2r[j];
#pragma unroll
        for (int k = 0; k < 64; k++) {
            float hk = h[k];
#pragma unroll
            for (int j = 0; j < 32; j++) fr[j] = fmaf(hk, cw2r[k * 32 + j], fr[j]);
        }
#pragma unroll
        for (int j = 0; j < 32; j++) fr[j] = fmaxf(fr[j], 0.0f);
    }

    // gates: comb = [fx, fr] (64) -> wax / war (64x32)
    float sx[32], sr[32];
#pragma unroll
    for (int j = 0; j < 32; j++) { sx[j] = cbax[j]; sr[j] = cbar[j]; }
#pragma unroll
    for (int k = 0; k < 32; k++) {
        float c = fx[k];
#pragma unroll
        for (int j = 0; j < 32; j++) {
            sx[j] = fmaf(c, cwax[k * 32 + j], sx[j]);
            sr[j] = fmaf(c, cwar[k * 32 + j], sr[j]);
        }
    }
#pragma unroll
    for (int k = 0; k < 32; k++) {
        float c = fr[k];
#pragma unroll
        for (int j = 0; j < 32; j++) {
            sx[j] = fmaf(c, cwax[(32 + k) * 32 + j], sx[j]);
            sr[j] = fmaf(c, cwar[(32 + k) * 32 + j], sr[j]);
        }
    }

    float *pb = g_pf2 + (size_t)i * 128;
    unsigned int *vb = g_voxmax + (size_t)v2p[i] * 128;

#pragma unroll
    for (int j = 0; j < 32; j += 4) {
        float4 o;
        // seg 0: fx
        o.x = fx[j]; o.y = fx[j + 1]; o.z = fx[j + 2]; o.w = fx[j + 3];
        *(float4 *)(pb + j) = o;
        atomicMax(vb + j + 0, __float_as_uint(o.x));
        atomicMax(vb + j + 1, __float_as_uint(o.y));
        atomicMax(vb + j + 2, __float_as_uint(o.z));
        atomicMax(vb + j + 3, __float_as_uint(o.w));
        // seg 1: fx * sigmoid(sx)
        o.x = fx[j] * sigm(sx[j]);       o.y = fx[j + 1] * sigm(sx[j + 1]);
        o.z = fx[j + 2] * sigm(sx[j + 2]); o.w = fx[j + 3] * sigm(sx[j + 3]);
        *(float4 *)(pb + 32 + j) = o;
        atomicMax(vb + 32 + j + 0, __float_as_uint(o.x));
        atomicMax(vb + 32 + j + 1, __float_as_uint(o.y));
        atomicMax(vb + 32 + j + 2, __float_as_uint(o.z));
        atomicMax(vb + 32 + j + 3, __float_as_uint(o.w));
        // seg 2: fr
        o.x = fr[j]; o.y = fr[j + 1]; o.z = fr[j + 2]; o.w = fr[j + 3];
        *(float4 *)(pb + 64 + j) = o;
        atomicMax(vb + 64 + j + 0, __float_as_uint(o.x));
        atomicMax(vb + 64 + j + 1, __float_as_uint(o.y));
        atomicMax(vb + 64 + j + 2, __float_as_uint(o.z));
        atomicMax(vb + 64 + j + 3, __float_as_uint(o.w));
        // seg 3: fr * sigmoid(sr)
        o.x = fr[j] * sigm(sr[j]);       o.y = fr[j + 1] * sigm(sr[j + 1]);
        o.z = fr[j + 2] * sigm(sr[j + 2]); o.w = fr[j + 3] * sigm(sr[j + 3]);
        *(float4 *)(pb + 96 + j) = o;
        atomicMax(vb + 96 + j + 0, __float_as_uint(o.x));
        atomicMax(vb + 96 + j + 1, __float_as_uint(o.y));
        atomicMax(vb + 96 + j + 2, __float_as_uint(o.z));
        atomicMax(vb + 96 + j + 3, __float_as_uint(o.w));
    }
}

// ---------------------------------------------------------------------------
// Generic relu-GEMM: out(M,NC) = relu(A(M,K) @ W(K,NC) + bias)
// 64-row tiles, 256 threads (16x16), 4 rows x NC/16 cols per thread, FFMA2.
// ---------------------------------------------------------------------------
template <int K, int NC>
__global__ __launch_bounds__(256, 2) void gemm_relu_kernel(
    const float *__restrict__ A, const float *__restrict__ W,
    const float *__restrict__ bias, float *__restrict__ out, int M)
{
    __shared__ float As[32 * 68];
    __shared__ float Ws[32 * NC];
    const int t = threadIdx.x, tx = t & 15, ty = t >> 4;
    const int m0 = blockIdx.x * 64;
    constexpr int CP = NC / 32;  // f32x2 accumulators per row

    unsigned long long acc[4][CP];
#pragma unroll
    for (int r = 0; r < 4; r++)
#pragma unroll
        for (int c = 0; c < CP; c++) acc[r][c] = 0ULL;

    for (int kc = 0; kc < K; kc += 32) {
        __syncthreads();
#pragma unroll
        for (int i = 0; i < 2; i++) {
            int s = t + 256 * i;
            int m = s >> 3, kq = (s & 7) << 2;
            int gr = m0 + m;
            float4 v = make_float4(0.f, 0.f, 0.f, 0.f);
            if (gr < M) v = *(const float4 *)(A + (size_t)gr * K + kc + kq);
            As[(kq + 0) * 68 + m] = v.x;
            As[(kq + 1) * 68 + m] = v.y;
            As[(kq + 2) * 68 + m] = v.z;
            As[(kq + 3) * 68 + m] = v.w;
        }
#pragma unroll
        for (int i = 0; i < NC / 32; i++) {
            int s = t + 256 * i;
            int k = s / (NC / 4), j = (s % (NC / 4)) * 4;
            *(float4 *)(Ws + k * NC + j) = *(const float4 *)(W + (size_t)(kc + k) * NC + j);
        }
        __syncthreads();
#pragma unroll
        for (int k = 0; k < 32; k++) {
            float4 a4 = *(const float4 *)(As + k * 68 + ty * 4);
            unsigned long long ap[4];
            ap[0] = pack2(a4.x); ap[1] = pack2(a4.y); ap[2] = pack2(a4.z); ap[3] = pack2(a4.w);
            const ulonglong2 *bp = (const ulonglong2 *)(Ws + k * NC + tx * (NC / 16));
#pragma unroll
            for (int q = 0; q < CP / 2; q++) {
                ulonglong2 b2 = bp[q];
#pragma unroll
                for (int r = 0; r < 4; r++) {
                    acc[r][2 * q]     = ffma2(ap[r], b2.x, acc[r][2 * q]);
                    acc[r][2 * q + 1] = ffma2(ap[r], b2.y, acc[r][2 * q + 1]);
                }
            }
        }
    }

#pragma unroll
    for (int r = 0; r < 4; r++) {
        int gr = m0 + ty * 4 + r;
        if (gr < M) {
            float *orow = out + (size_t)gr * NC + tx * (NC / 16);
            const float *brow = bias + tx * (NC / 16);
#pragma unroll
            for (int c = 0; c < CP; c++) {
                float lo, hi;
                unpack2(acc[r][c], lo, hi);
                lo = fmaxf(lo + brow[2 * c], 0.f);
                hi = fmaxf(hi + brow[2 * c + 1], 0.f);
                orow[2 * c] = lo;
                orow[2 * c + 1] = hi;
            }
        }
    }
}

// ---------------------------------------------------------------------------
// Fused w3 + w4 kernel:
//   pf3[i] = [ voxw[idx[i]] (128) | pf2[i] (128) ]
//   mid    = relu(pf3 @ w3 + b3)            (kept in shared)
//   pf5    = relu(mid @ w4 + b4)            -> atomicMax into vox2[idx[i]]
// ---------------------------------------------------------------------------
__global__ __launch_bounds__(256, 2) void fused_w3w4_kernel(
    const float *__restrict__ pf2, const float *__restrict__ voxw,
    const int *__restrict__ v2p,
    const float *__restrict__ w3, const float *__restrict__ b3,
    const float *__restrict__ w4, const float *__restrict__ b4,
    unsigned int *__restrict__ vox2, int N)
{
    extern __shared__ float sm[];
    float *As  = sm;                   // 32 * 68  = 2176 floats
    float *Ws  = sm + 2176;            // 32 * 256 = 8192 floats
    float *mid = sm + 2176 + 8192;     // 64 * 264 = 16896 floats
    int *sIdx  = (int *)(sm + 27264);  // 64 ints

    const int t = threadIdx.x, tx = t & 15, ty = t >> 4;
    const int m0 = blockIdx.x * 64;

    if (t < 64) {
        int gr = m0 + t;
        sIdx[t] = (gr < N) ? v2p[gr] : 0;
    }

    unsigned long long acc[4][8];
#pragma unroll
    for (int r = 0; r < 4; r++)
#pragma unroll
        for (int c = 0; c < 8; c++) acc[r][c] = 0ULL;

    // ---- stage A: mid = relu(pf3 @ w3 + b3) ----
    for (int kc = 0; kc < 256; kc += 32) {
        __syncthreads();
#pragma unroll
        for (int i = 0; i < 2; i++) {
            int s = t + 256 * i;
            int m = s >> 3, kq = (s & 7) << 2;
            int gk = kc + kq, gr = m0 + m;
            float4 v = make_float4(0.f, 0.f, 0.f, 0.f);
            if (gr < N) {
                if (gk < 128) v = *(const float4 *)(voxw + (size_t)sIdx[m] * 128 + gk);
                else          v = *(const float4 *)(pf2 + (size_t)gr * 128 + (gk - 128));
            }
            As[(kq + 0) * 68 + m] = v.x;
            As[(kq + 1) * 68 + m] = v.y;
            As[(kq + 2) * 68 + m] = v.z;
            As[(kq + 3) * 68 + m] = v.w;
        }
#pragma unroll
        for (int i = 0; i < 8; i++) {
            int s = t + 256 * i;
            int k = s >> 6, j = (s & 63) << 2;
            *(float4 *)(Ws + k * 256 + j) = *(const float4 *)(w3 + (size_t)(kc + k) * 256 + j);
        }
        __syncthreads();
#pragma unroll
        for (int k = 0; k < 32; k++) {
            float4 a4 = *(const float4 *)(As + k * 68 + ty * 4);
            unsigned long long ap[4];
            ap[0] = pack2(a4.x); ap[1] = pack2(a4.y); ap[2] = pack2(a4.z); ap[3] = pack2(a4.w);
            const ulonglong2 *bp = (const ulonglong2 *)(Ws + k * 256 + tx * 16);
#pragma unroll
            for (int q = 0; q < 4; q++) {
                ulonglong2 b2 = bp[q];
#pragma unroll
                for (int r = 0; r < 4; r++) {
                    acc[r][2 * q]     = ffma2(ap[r], b2.x, acc[r][2 * q]);
                    acc[r][2 * q + 1] = ffma2(ap[r], b2.y, acc[r][2 * q + 1]);
                }
            }
        }
    }

    // bias + relu -> shared mid, reset acc
#pragma unroll
    for (int r = 0; r < 4; r++) {
        float *mrow = mid + (ty * 4 + r) * 264 + tx * 16;
        const float *brow = b3 + tx * 16;
#pragma unroll
        for (int c = 0; c < 8; c++) {
            float lo, hi;
            unpack2(acc[r][c], lo, hi);
            lo = fmaxf(lo + brow[2 * c], 0.f);
            hi = fmaxf(hi + brow[2 * c + 1], 0.f);
            mrow[2 * c] = lo;
            mrow[2 * c + 1] = hi;
            acc[r][c] = 0ULL;
        }
    }

    // ---- stage B: pf5 = relu(mid @ w4 + b4) -> atomic seg-max ----
    for (int kc = 0; kc < 256; kc += 32) {
        __syncthreads();  // mid fully written / previous Ws reads done
#pragma unroll
        for (int i = 0; i < 8; i++) {
            int s = t + 256 * i;
            int k = s >> 6, j = (s & 63) << 2;
            *(float4 *)(Ws + k * 256 + j) = *(const float4 *)(w4 + (size_t)(kc + k) * 256 + j);
        }
        __syncthreads();
#pragma unroll
        for (int k = 0; k < 32; k++) {
            int gk = kc + k;
            unsigned long long ap[4];
            ap[0] = pack2(mid[(ty * 4 + 0) * 264 + gk]);
            ap[1] = pack2(mid[(ty * 4 + 1) * 264 + gk]);
            ap[2] = pack2(mid[(ty * 4 + 2) * 264 + gk]);
            ap[3] = pack2(mid[(ty * 4 + 3) * 264 + gk]);
            const ulonglong2 *bp = (const ulonglong2 *)(Ws + k * 256 + tx * 16);
#pragma unroll
            for (int q = 0; q < 4; q++) {
                ulonglong2 b2 = bp[q];
#pragma unroll
                for (int r = 0; r < 4; r++) {
                    acc[r][2 * q]     = ffma2(ap[r], b2.x, acc[r][2 * q]);
                    acc[r][2 * q + 1] = ffma2(ap[r], b2.y, acc[r][2 * q + 1]);
                }
            }
        }
    }

#pragma unroll
    for (int r = 0; r < 4; r++) {
        int gr = m0 + ty * 4 + r;
        if (gr < N) {
            unsigned int *orow = vox2 + (size_t)sIdx[ty * 4 + r] * 256 + tx * 16;
            const float *brow = b4 + tx * 16;
#pragma unroll
            for (int c = 0; c < 8; c++) {
                float lo, hi;
                unpack2(acc[r][c], lo, hi);
                lo = fmaxf(lo + brow[2 * c], 0.f);
                hi = fmaxf(hi + brow[2 * c + 1], 0.f);
                atomicMax(orow + 2 * c,     __float_as_uint(lo));
                atomicMax(orow + 2 * c + 1, __float_as_uint(hi));
            }
        }
    }
}

// ---------------------------------------------------------------------------
// Launch
// ---------------------------------------------------------------------------
extern "C" void kernel_launch(void *const *d_in, const int *in_sizes, int n_in,
                              void *d_out, int out_size)
{
    const float *inp = (const float *)d_in[0];
    const int *v2p   = (const int *)d_in[1];
    // d_in[2] = num_vox (scalar) — derived from out_size instead
    const float *w1x = (const float *)d_in[3],  *b1x = (const float *)d_in[4];
    const float *w2x = (const float *)d_in[5],  *b2x = (const float *)d_in[6];
    const float *w1r = (const float *)d_in[7],  *b1r = (const float *)d_in[8];
    const float *w2r = (const float *)d_in[9],  *b2r = (const float *)d_in[10];
    const float *wax = (const float *)d_in[11], *bax = (const float *)d_in[12];
    const float *war = (const float *)d_in[13], *bar = (const float *)d_in[14];
    const float *wv1 = (const float *)d_in[15], *bv1 = (const float *)d_in[16];
    const float *w3  = (const float *)d_in[17], *b3  = (const float *)d_in[18];
    const float *w4  = (const float *)d_in[19], *b4  = (const float *)d_in[20];
    const float *wv2 = (const float *)d_in[21], *bv2 = (const float *)d_in[22];

    int N = in_sizes[0] / 6;
    int V = out_size / 256;

    void *p_pf2, *p_voxmax, *p_voxw, *p_vox2;
    cudaGetSymbolAddress(&p_pf2, g_pf2);
    cudaGetSymbolAddress(&p_voxmax, g_voxmax);
    cudaGetSymbolAddress(&p_voxw, g_voxw);
    cudaGetSymbolAddress(&p_vox2, g_vox2);

    // 0) zero segment-max buffers
    zero_kernel<<<(V * 96 + 255) / 256, 256>>>(V);

    // 1) stage-1 MLPs + gates -> pf2, seg-max #1
    stage1_kernel<<<(N + 127) / 128, 128>>>(inp, v2p,
                                            w1x, b1x, w2x, b2x,
                                            w1r, b1r, w2r, b2r,
                                            wax, bax, war, bar, N);

    // 2) voxw = relu(voxmax @ wv1 + bv1)
    gemm_relu_kernel<128, 128><<<(V + 63) / 64, 256>>>(
        (const float *)p_voxmax, wv1, bv1, (float *)p_voxw, V);

    // 3) fused w3/w4 + gather + seg-max #2
    int smem_bytes = (2176 + 8192 + 16896) * 4 + 64 * 4;  // 109312
    cudaFuncSetAttribute(fused_w3w4_kernel,
                         cudaFuncAttributeMaxDynamicSharedMemorySize, smem_bytes);
    fused_w3w4_kernel<<<(N + 63) / 64, 256, smem_bytes>>>(
        (const float *)p_pf2, (const float *)p_voxw, v2p,
        w3, b3, w4, b4, (unsigned int *)p_vox2, N);

    // 4) out = relu(vox2 @ wv2 + bv2)
    gemm_relu_kernel<256, 256><<<(V + 63) / 64, 256>>>(
        (const float *)p_vox2, wv2, bv2, (float *)d_out, V);
}

// round 10
// speedup vs baseline: 2.4761x; 2.4761x over previous
#include <cuda_runtime.h>
#include <cuda_bf16.h>
#include <math.h>

// ---------------------------------------------------------------------------
// Problem constants (shapes fixed by the dataset)
// ---------------------------------------------------------------------------
#define MAXN 500000
#define MAXV 50000

// Scratch (device globals: allocation-free rule)
__device__ float        g_pf2[(size_t)MAXN * 128];     // 256 MB point features stage-1
__device__ unsigned int g_voxmax[(size_t)MAXV * 128];  // segment-max #1 (bits of nonneg f32)
__device__ float        g_voxw[(size_t)MAXV * 128];    // relu(vox @ wv1 + bv1)
__device__ unsigned int g_vox2[(size_t)MAXV * 256];    // segment-max #2

// ---------------------------------------------------------------------------
// Packed f32x2 helpers (Blackwell FFMA2 — 2x fp32 FMA rate)
// ---------------------------------------------------------------------------
__device__ __forceinline__ unsigned long long pack2(float x) {
    unsigned long long r;
    asm("mov.b64 %0, {%1, %1};" : "=l"(r) : "f"(x));
    return r;
}
__device__ __forceinline__ void unpack2(unsigned long long v, float &lo, float &hi) {
    asm("mov.b64 {%0, %1}, %2;" : "=f"(lo), "=f"(hi) : "l"(v));
}
__device__ __forceinline__ unsigned long long ffma2(unsigned long long a,
                                                    unsigned long long b,
                                                    unsigned long long c) {
    unsigned long long d;
    asm("fma.rn.f32x2 %0, %1, %2, %3;" : "=l"(d) : "l"(a), "l"(b), "l"(c));
    return d;
}

__device__ __forceinline__ float sigm(float s) { return 1.0f / (1.0f + expf(-s)); }

// ---------------------------------------------------------------------------
// Kernel 0: zero the two segment-max buffers
// ---------------------------------------------------------------------------
__global__ void zero_kernel(int V) {
    int i = blockIdx.x * blockDim.x + threadIdx.x;
    int n1 = V * 32;  // voxmax in uint4 units (V*128/4)
    int n2 = V * 64;  // vox2   in uint4 units (V*256/4)
    uint4 z = {0u, 0u, 0u, 0u};
    if (i < n1)            ((uint4 *)g_voxmax)[i]      = z;
    else if (i < n1 + n2)  ((uint4 *)g_vox2)[i - n1]   = z;
}

// ---------------------------------------------------------------------------
// Kernel 1: per-point stage-1 MLPs + gates -> pf2 (N,128) + atomic seg-max #1
// ---------------------------------------------------------------------------
__global__ __launch_bounds__(128, 1) void stage1_kernel(
    const float *__restrict__ inp, const int *__restrict__ v2p,
    const float *__restrict__ w1x, const float *__restrict__ b1x,
    const float *__restrict__ w2x, const float *__restrict__ b2x,
    const float *__restrict__ w1r, const float *__restrict__ b1r,
    const float *__restrict__ w2r, const float *__restrict__ b2r,
    const float *__restrict__ wax, const float *__restrict__ bax,
    const float *__restrict__ war, const float *__restrict__ bar,
    int N)
{
    __shared__ float sW[8832];
    const int t = threadIdx.x;
    {
        const float *srcs[12] = {w1x, b1x, w2x, b2x, w1r, b1r, w2r, b2r, wax, bax, war, bar};
        const int offs[13] = {0, 192, 256, 2304, 2336, 2528, 2592, 4640, 4672, 6720, 6752, 8800, 8832};
        for (int a = 0; a < 12; a++) {
            int n = offs[a + 1] - offs[a];
            for (int s = t; s < n; s += 128) sW[offs[a] + s] = srcs[a][s];
        }
    }
    __syncthreads();

    int i = blockIdx.x * 128 + t;
    if (i >= N) return;

    const float *cw1x = sW;        const float *cb1x = sW + 192;
    const float *cw2x = sW + 256;  const float *cb2x = sW + 2304;
    const float *cw1r = sW + 2336; const float *cb1r = sW + 2528;
    const float *cw2r = sW + 2592; const float *cb2r = sW + 4640;
    const float *cwax = sW + 4672; const float *cbax = sW + 6720;
    const float *cwar = sW + 6752; const float *cbar = sW + 8800;

    const float *pi = inp + (size_t)i * 6;
    float p0 = pi[0], p1 = pi[1], p2 = pi[2], p3 = pi[3], p4 = pi[4], p5 = pi[5];

    float fx[32], fr[32];
    {
        float h[64];
#pragma unroll
        for (int j = 0; j < 64; j++)
            h[j] = fmaxf(cb1x[j] + p0 * cw1x[j] + p1 * cw1x[64 + j] + p2 * cw1x[128 + j], 0.0f);
#pragma unroll
        for (int j = 0; j < 32; j++) fx[j] = cb2x[j];
#pragma unroll
        for (int k = 0; k < 64; k++) {
            float hk = h[k];
#pragma unroll
            for (int j = 0; j < 32; j++) fx[j] = fmaf(hk, cw2x[k * 32 + j], fx[j]);
        }
#pragma unroll
        for (int j = 0; j < 32; j++) fx[j] = fmaxf(fx[j], 0.0f);
    }
    {
        float h[64];
#pragma unroll
        for (int j = 0; j < 64; j++)
            h[j] = fmaxf(cb1r[j] + p3 * cw1r[j] + p4 * cw1r[64 + j] + p5 * cw1r[128 + j], 0.0f);
#pragma unroll
        for (int j = 0; j < 32; j++) fr[j] = cb2r[j];
#pragma unroll
        for (int k = 0; k < 64; k++) {
            float hk = h[k];
#pragma unroll
            for (int j = 0; j < 32; j++) fr[j] = fmaf(hk, cw2r[k * 32 + j], fr[j]);
        }
#pragma unroll
        for (int j = 0; j < 32; j++) fr[j] = fmaxf(fr[j], 0.0f);
    }

    // gates: comb = [fx, fr] (64) -> wax / war (64x32)
    float sx[32], sr[32];
#pragma unroll
    for (int j = 0; j < 32; j++) { sx[j] = cbax[j]; sr[j] = cbar[j]; }
#pragma unroll
    for (int k = 0; k < 32; k++) {
        float c = fx[k];
#pragma unroll
        for (int j = 0; j < 32; j++) {
            sx[j] = fmaf(c, cwax[k * 32 + j], sx[j]);
            sr[j] = fmaf(c, cwar[k * 32 + j], sr[j]);
        }
    }
#pragma unroll
    for (int k = 0; k < 32; k++) {
        float c = fr[k];
#pragma unroll
        for (int j = 0; j < 32; j++) {
            sx[j] = fmaf(c, cwax[(32 + k) * 32 + j], sx[j]);
            sr[j] = fmaf(c, cwar[(32 + k) * 32 + j], sr[j]);
        }
    }

    float *pb = g_pf2 + (size_t)i * 128;
    unsigned int *vb = g_voxmax + (size_t)v2p[i] * 128;

#pragma unroll
    for (int j = 0; j < 32; j += 4) {
        float4 o;
        // seg 0: fx
        o.x = fx[j]; o.y = fx[j + 1]; o.z = fx[j + 2]; o.w = fx[j + 3];
        *(float4 *)(pb + j) = o;
        atomicMax(vb + j + 0, __float_as_uint(o.x));
        atomicMax(vb + j + 1, __float_as_uint(o.y));
        atomicMax(vb + j + 2, __float_as_uint(o.z));
        atomicMax(vb + j + 3, __float_as_uint(o.w));
        // seg 1: fx * sigmoid(sx)
        o.x = fx[j] * sigm(sx[j]);       o.y = fx[j + 1] * sigm(sx[j + 1]);
        o.z = fx[j + 2] * sigm(sx[j + 2]); o.w = fx[j + 3] * sigm(sx[j + 3]);
        *(float4 *)(pb + 32 + j) = o;
        atomicMax(vb + 32 + j + 0, __float_as_uint(o.x));
        atomicMax(vb + 32 + j + 1, __float_as_uint(o.y));
        atomicMax(vb + 32 + j + 2, __float_as_uint(o.z));
        atomicMax(vb + 32 + j + 3, __float_as_uint(o.w));
        // seg 2: fr
        o.x = fr[j]; o.y = fr[j + 1]; o.z = fr[j + 2]; o.w = fr[j + 3];
        *(float4 *)(pb + 64 + j) = o;
        atomicMax(vb + 64 + j + 0, __float_as_uint(o.x));
        atomicMax(vb + 64 + j + 1, __float_as_uint(o.y));
        atomicMax(vb + 64 + j + 2, __float_as_uint(o.z));
        atomicMax(vb + 64 + j + 3, __float_as_uint(o.w));
        // seg 3: fr * sigmoid(sr)
        o.x = fr[j] * sigm(sr[j]);       o.y = fr[j + 1] * sigm(sr[j + 1]);
        o.z = fr[j + 2] * sigm(sr[j + 2]); o.w = fr[j + 3] * sigm(sr[j + 3]);
        *(float4 *)(pb + 96 + j) = o;
        atomicMax(vb + 96 + j + 0, __float_as_uint(o.x));
        atomicMax(vb + 96 + j + 1, __float_as_uint(o.y));
        atomicMax(vb + 96 + j + 2, __float_as_uint(o.z));
        atomicMax(vb + 96 + j + 3, __float_as_uint(o.w));
    }
}

// ---------------------------------------------------------------------------
// Generic relu-GEMM: out(M,NC) = relu(A(M,K) @ W(K,NC) + bias)
// 64-row tiles, 256 threads (16x16). Thread (tx,ty) owns rows ty*4..+3 and
// columns {q*64 + tx*4 .. +3 | q < NC/64}  -> every B LDS.128 has 16 lanes at
// consecutive 16B addresses: conflict-free (2-wavefront minimum).
// ---------------------------------------------------------------------------
template <int K, int NC>
__global__ __launch_bounds__(256, 2) void gemm_relu_kernel(
    const float *__restrict__ A, const float *__restrict__ W,
    const float *__restrict__ bias, float *__restrict__ out, int M)
{
    __shared__ float As[32 * 68];
    __shared__ float Ws[32 * NC];
    const int t = threadIdx.x, tx = t & 15, ty = t >> 4;
    const int m0 = blockIdx.x * 64;
    constexpr int NQ = NC / 64;  // column groups per thread

    unsigned long long acc[4][2 * NQ];
#pragma unroll
    for (int r = 0; r < 4; r++)
#pragma unroll
        for (int c = 0; c < 2 * NQ; c++) acc[r][c] = 0ULL;

    for (int kc = 0; kc < K; kc += 32) {
        __syncthreads();
#pragma unroll
        for (int i = 0; i < 2; i++) {
            int s = t + 256 * i;
            int m = s >> 3, kq = (s & 7) << 2;
            int gr = m0 + m;
            float4 v = make_float4(0.f, 0.f, 0.f, 0.f);
            if (gr < M) v = *(const float4 *)(A + (size_t)gr * K + kc + kq);
            As[(kq + 0) * 68 + m] = v.x;
            As[(kq + 1) * 68 + m] = v.y;
            As[(kq + 2) * 68 + m] = v.z;
            As[(kq + 3) * 68 + m] = v.w;
        }
#pragma unroll
        for (int i = 0; i < NC / 32; i++) {
            int s = t + 256 * i;
            int k = s / (NC / 4), j = (s % (NC / 4)) * 4;
            *(float4 *)(Ws + k * NC + j) = *(const float4 *)(W + (size_t)(kc + k) * NC + j);
        }
        __syncthreads();
#pragma unroll
        for (int k = 0; k < 32; k++) {
            float4 a4 = *(const float4 *)(As + k * 68 + ty * 4);
            unsigned long long ap[4];
            ap[0] = pack2(a4.x); ap[1] = pack2(a4.y); ap[2] = pack2(a4.z); ap[3] = pack2(a4.w);
#pragma unroll
            for (int q = 0; q < NQ; q++) {
                ulonglong2 b2 = *(const ulonglong2 *)(Ws + k * NC + q * 64 + tx * 4);
#pragma unroll
                for (int r = 0; r < 4; r++) {
                    acc[r][2 * q]     = ffma2(ap[r], b2.x, acc[r][2 * q]);
                    acc[r][2 * q + 1] = ffma2(ap[r], b2.y, acc[r][2 * q + 1]);
                }
            }
        }
    }

#pragma unroll
    for (int r = 0; r < 4; r++) {
        int gr = m0 + ty * 4 + r;
        if (gr < M) {
#pragma unroll
            for (int q = 0; q < NQ; q++) {
                int c0 = q * 64 + tx * 4;
                float lo0, hi0, lo1, hi1;
                unpack2(acc[r][2 * q], lo0, hi0);
                unpack2(acc[r][2 * q + 1], lo1, hi1);
                float4 o;
                o.x = fmaxf(lo0 + bias[c0 + 0], 0.f);
                o.y = fmaxf(hi0 + bias[c0 + 1], 0.f);
                o.z = fmaxf(lo1 + bias[c0 + 2], 0.f);
                o.w = fmaxf(hi1 + bias[c0 + 3], 0.f);
                *(float4 *)(out + (size_t)gr * NC + c0) = o;
            }
        }
    }
}

// ---------------------------------------------------------------------------
// Fused w3 + w4 kernel (conflict-free column mapping):
//   pf3[i] = [ voxw[idx[i]] (128) | pf2[i] (128) ]
//   mid    = relu(pf3 @ w3 + b3)            (kept in shared)
//   pf5    = relu(mid @ w4 + b4)            -> atomicMax into vox2[idx[i]]
// ---------------------------------------------------------------------------
__global__ __launch_bounds__(256, 2) void fused_w3w4_kernel(
    const float *__restrict__ pf2, const float *__restrict__ voxw,
    const int *__restrict__ v2p,
    const float *__restrict__ w3, const float *__restrict__ b3,
    const float *__restrict__ w4, const float *__restrict__ b4,
    unsigned int *__restrict__ vox2, int N)
{
    extern __shared__ float sm[];
    float *As  = sm;                   // 32 * 68  = 2176 floats
    float *Ws  = sm + 2176;            // 32 * 256 = 8192 floats
    float *mid = sm + 2176 + 8192;     // 64 * 264 = 16896 floats
    int *sIdx  = (int *)(sm + 27264);  // 64 ints

    const int t = threadIdx.x, tx = t & 15, ty = t >> 4;
    const int m0 = blockIdx.x * 64;

    if (t < 64) {
        int gr = m0 + t;
        sIdx[t] = (gr < N) ? v2p[gr] : 0;
    }

    unsigned long long acc[4][8];
#pragma unroll
    for (int r = 0; r < 4; r++)
#pragma unroll
        for (int c = 0; c < 8; c++) acc[r][c] = 0ULL;

    // ---- stage A: mid = relu(pf3 @ w3 + b3) ----
    for (int kc = 0; kc < 256; kc += 32) {
        __syncthreads();
#pragma unroll
        for (int i = 0; i < 2; i++) {
            int s = t + 256 * i;
            int m = s >> 3, kq = (s & 7) << 2;
            int gk = kc + kq, gr = m0 + m;
            float4 v = make_float4(0.f, 0.f, 0.f, 0.f);
            if (gr < N) {
                if (gk < 128) v = *(const float4 *)(voxw + (size_t)sIdx[m] * 128 + gk);
                else          v = *(const float4 *)(pf2 + (size_t)gr * 128 + (gk - 128));
            }
            As[(kq + 0) * 68 + m] = v.x;
            As[(kq + 1) * 68 + m] = v.y;
            As[(kq + 2) * 68 + m] = v.z;
            As[(kq + 3) * 68 + m] = v.w;
        }
#pragma unroll
        for (int i = 0; i < 8; i++) {
            int s = t + 256 * i;
            int k = s >> 6, j = (s & 63) << 2;
            *(float4 *)(Ws + k * 256 + j) = *(const float4 *)(w3 + (size_t)(kc + k) * 256 + j);
        }
        __syncthreads();
#pragma unroll
        for (int k = 0; k < 32; k++) {
            float4 a4 = *(const float4 *)(As + k * 68 + ty * 4);
            unsigned long long ap[4];
            ap[0] = pack2(a4.x); ap[1] = pack2(a4.y); ap[2] = pack2(a4.z); ap[3] = pack2(a4.w);
#pragma unroll
            for (int q = 0; q < 4; q++) {
                ulonglong2 b2 = *(const ulonglong2 *)(Ws + k * 256 + q * 64 + tx * 4);
#pragma unroll
                for (int r = 0; r < 4; r++) {
                    acc[r][2 * q]     = ffma2(ap[r], b2.x, acc[r][2 * q]);
                    acc[r][2 * q + 1] = ffma2(ap[r], b2.y, acc[r][2 * q + 1]);
                }
            }
        }
    }

    // bias + relu -> shared mid, reset acc
#pragma unroll
    for (int r = 0; r < 4; r++) {
        float *mrow = mid + (ty * 4 + r) * 264;
#pragma unroll
        for (int q = 0; q < 4; q++) {
            int c0 = q * 64 + tx * 4;
            float lo0, hi0, lo1, hi1;
            unpack2(acc[r][2 * q], lo0, hi0);
            unpack2(acc[r][2 * q + 1], lo1, hi1);
            float4 o;
            o.x = fmaxf(lo0 + b3[c0 + 0], 0.f);
            o.y = fmaxf(hi0 + b3[c0 + 1], 0.f);
            o.z = fmaxf(lo1 + b3[c0 + 2], 0.f);
            o.w = fmaxf(hi1 + b3[c0 + 3], 0.f);
            *(float4 *)(mrow + c0) = o;
            acc[r][2 * q] = 0ULL;
            acc[r][2 * q + 1] = 0ULL;
        }
    }

    // ---- stage B: pf5 = relu(mid @ w4 + b4) -> atomic seg-max ----
    for (int kc = 0; kc < 256; kc += 32) {
        __syncthreads();  // mid fully written / previous Ws reads done
#pragma unroll
        for (int i = 0; i < 8; i++) {
            int s = t + 256 * i;
            int k = s >> 6, j = (s & 63) << 2;
            *(float4 *)(Ws + k * 256 + j) = *(const float4 *)(w4 + (size_t)(kc + k) * 256 + j);
        }
        __syncthreads();
        // Vectorized mid reads: one broadcast float4 per row per 4 k-steps.
#pragma unroll
        for (int k4 = 0; k4 < 32; k4 += 4) {
            float4 am[4];
#pragma unroll
            for (int r = 0; r < 4; r++)
                am[r] = *(const float4 *)(mid + (ty * 4 + r) * 264 + kc + k4);
#pragma unroll
            for (int kk = 0; kk < 4; kk++) {
                int k = k4 + kk;
                unsigned long long ap[4];
                ap[0] = pack2(((const float *)&am[0])[kk]);
                ap[1] = pack2(((const float *)&am[1])[kk]);
                ap[2] = pack2(((const float *)&am[2])[kk]);
                ap[3] = pack2(((const float *)&am[3])[kk]);
#pragma unroll
                for (int q = 0; q < 4; q++) {
                    ulonglong2 b2 = *(const ulonglong2 *)(Ws + k * 256 + q * 64 + tx * 4);
#pragma unroll
                    for (int r = 0; r < 4; r++) {
                        acc[r][2 * q]     = ffma2(ap[r], b2.x, acc[r][2 * q]);
                        acc[r][2 * q + 1] = ffma2(ap[r], b2.y, acc[r][2 * q + 1]);
                    }
                }
            }
        }
    }

#pragma unroll
    for (int r = 0; r < 4; r++) {
        int gr = m0 + ty * 4 + r;
        if (gr < N) {
            unsigned int *orow = vox2 + (size_t)sIdx[ty * 4 + r] * 256;
#pragma unroll
            for (int q = 0; q < 4; q++) {
                int c0 = q * 64 + tx * 4;
                float lo0, hi0, lo1, hi1;
                unpack2(acc[r][2 * q], lo0, hi0);
                unpack2(acc[r][2 * q + 1], lo1, hi1);
                atomicMax(orow + c0 + 0, __float_as_uint(fmaxf(lo0 + b4[c0 + 0], 0.f)));
                atomicMax(orow + c0 + 1, __float_as_uint(fmaxf(hi0 + b4[c0 + 1], 0.f)));
                atomicMax(orow + c0 + 2, __float_as_uint(fmaxf(lo1 + b4[c0 + 2], 0.f)));
                atomicMax(orow + c0 + 3, __float_as_uint(fmaxf(hi1 + b4[c0 + 3], 0.f)));
            }
        }
    }
}

// ---------------------------------------------------------------------------
// Launch
// ---------------------------------------------------------------------------
extern "C" void kernel_launch(void *const *d_in, const int *in_sizes, int n_in,
                              void *d_out, int out_size)
{
    const float *inp = (const float *)d_in[0];
    const int *v2p   = (const int *)d_in[1];
    // d_in[2] = num_vox (scalar) — derived from out_size instead
    const float *w1x = (const float *)d_in[3],  *b1x = (const float *)d_in[4];
    const float *w2x = (const float *)d_in[5],  *b2x = (const float *)d_in[6];
    const float *w1r = (const float *)d_in[7],  *b1r = (const float *)d_in[8];
    const float *w2r = (const float *)d_in[9],  *b2r = (const float *)d_in[10];
    const float *wax = (const float *)d_in[11], *bax = (const float *)d_in[12];
    const float *war = (const float *)d_in[13], *bar = (const float *)d_in[14];
    const float *wv1 = (const float *)d_in[15], *bv1 = (const float *)d_in[16];
    const float *w3  = (const float *)d_in[17], *b3  = (const float *)d_in[18];
    const float *w4  = (const float *)d_in[19], *b4  = (const float *)d_in[20];
    const float *wv2 = (const float *)d_in[21], *bv2 = (const float *)d_in[22];

    int N = in_sizes[0] / 6;
    int V = out_size / 256;

    void *p_pf2, *p_voxmax, *p_voxw, *p_vox2;
    cudaGetSymbolAddress(&p_pf2, g_pf2);
    cudaGetSymbolAddress(&p_voxmax, g_voxmax);
    cudaGetSymbolAddress(&p_voxw, g_voxw);
    cudaGetSymbolAddress(&p_vox2, g_vox2);

    // 0) zero segment-max buffers
    zero_kernel<<<(V * 96 + 255) / 256, 256>>>(V);

    // 1) stage-1 MLPs + gates -> pf2, seg-max #1
    stage1_kernel<<<(N + 127) / 128, 128>>>(inp, v2p,
                                            w1x, b1x, w2x, b2x,
                                            w1r, b1r, w2r, b2r,
                                            wax, bax, war, bar, N);

    // 2) voxw = relu(voxmax @ wv1 + bv1)
    gemm_relu_kernel<128, 128><<<(V + 63) / 64, 256>>>(
        (const float *)p_voxmax, wv1, bv1, (float *)p_voxw, V);

    // 3) fused w3/w4 + gather + seg-max #2
    int smem_bytes = (2176 + 8192 + 16896) * 4 + 64 * 4;  // 109312
    cudaFuncSetAttribute(fused_w3w4_kernel,
                         cudaFuncAttributeMaxDynamicSharedMemorySize, smem_bytes);
    fused_w3w4_kernel<<<(N + 63) / 64, 256, smem_bytes>>>(
        (const float *)p_pf2, (const float *)p_voxw, v2p,
        w3, b3, w4, b4, (unsigned int *)p_vox2, N);

    // 4) out = relu(vox2 @ wv2 + bv2)
    gemm_relu_kernel<256, 256><<<(V + 63) / 64, 256>>>(
        (const float *)p_vox2, wv2, bv2, (float *)d_out, V);
}